// round 2
// baseline (speedup 1.0000x reference)
#include <cuda_runtime.h>
#include <cstdint>

#define HDIM   512
#define TLEN   2048
#define NBATCH 16
#define CLSZ   8

// ---------------- PTX helpers ----------------
__device__ __forceinline__ uint32_t smem_u32(const void* p) {
    uint32_t a;
    asm("{ .reg .u64 t; cvta.to.shared.u64 t, %1; cvt.u32.u64 %0, t; }" : "=r"(a) : "l"(p));
    return a;
}
// packed 2x fp32 FMA (FFMA2): d = a*b + d, elementwise on (lo,hi)
__device__ __forceinline__ void fma2(unsigned long long& d, unsigned long long a, unsigned long long b) {
    asm("fma.rn.f32x2 %0, %1, %2, %0;" : "+l"(d) : "l"(a), "l"(b));
}
__device__ __forceinline__ unsigned long long pk2(float lo, float hi) {
    unsigned long long r;
    asm("mov.b64 %0, {%1, %2};" : "=l"(r) : "f"(lo), "f"(hi));
    return r;
}
__device__ __forceinline__ float lo32(unsigned long long v) { return __uint_as_float((unsigned)(v & 0xffffffffull)); }
__device__ __forceinline__ float hi32(unsigned long long v) { return __uint_as_float((unsigned)(v >> 32)); }
__device__ __forceinline__ uint32_t mapa32(uint32_t a, uint32_t r) {
    uint32_t d; asm("mapa.shared::cluster.u32 %0, %1, %2;" : "=r"(d) : "r"(a), "r"(r)); return d;
}
__device__ __forceinline__ void st_async32(uint32_t ra, uint32_t v, uint32_t rb) {
    asm volatile("st.async.shared::cluster.mbarrier::complete_tx::bytes.b32 [%0], %1, [%2];"
                 :: "r"(ra), "r"(v), "r"(rb) : "memory");
}
__device__ __forceinline__ void mbar_init(uint32_t m, uint32_t cnt) {
    asm volatile("mbarrier.init.shared.b64 [%0], %1;" :: "r"(m), "r"(cnt) : "memory");
}
__device__ __forceinline__ void mbar_expect_tx(uint32_t m, uint32_t bytes) {
    asm volatile("mbarrier.arrive.expect_tx.shared.b64 _, [%0], %1;" :: "r"(m), "r"(bytes) : "memory");
}
__device__ __forceinline__ void mbar_wait_parity(uint32_t m, uint32_t parity) {
    asm volatile(
        "{\n\t"
        ".reg .pred P;\n"
        "LW_%=:\n\t"
        "mbarrier.try_wait.parity.acquire.cluster.shared::cta.b64 P, [%0], %1, 0x989680;\n\t"
        "@!P bra LW_%=;\n\t"
        "}"
        :: "r"(m), "r"(parity) : "memory");
}
__device__ __forceinline__ void cluster_sync_() {
    asm volatile("barrier.cluster.arrive.aligned;" ::: "memory");
    asm volatile("barrier.cluster.wait.aligned;" ::: "memory");
}

// ---------------- Phase 1: pre = X @ W_xh + b  (M=32768, N=512, K=512) ----------------
// 128x64 block tile, BK=16, 256 threads, each thread 8x4 microtile. Plain fp32.
__global__ __launch_bounds__(256) void pre_gemm(
    const float* __restrict__ X, const float* __restrict__ W,
    const float* __restrict__ bias, float* __restrict__ P)
{
    __shared__ __align__(16) float As[16][130];  // [k][m], padded (bank-safe, 8B-aligned rows)
    __shared__ __align__(16) float Bs[16][64];   // [k][n]
    const int tid = threadIdx.x;
    const int tx  = tid & 15;   // n subtile (4 cols)
    const int ty  = tid >> 4;   // m subtile (8 rows)
    const int m0  = blockIdx.x * 128;
    const int n0  = blockIdx.y * 64;

    const int arow = tid >> 1;         // 0..127
    const int ak   = (tid & 1) * 8;    // k offset 0 or 8
    const int bk   = tid >> 4;         // 0..15
    const int bn   = (tid & 15) * 4;

    float acc[8][4];
    #pragma unroll
    for (int i = 0; i < 8; i++)
        #pragma unroll
        for (int j = 0; j < 4; j++) acc[i][j] = 0.0f;

    for (int kb = 0; kb < 32; kb++) {
        const int k0 = kb * 16;
        const float* Xp = X + (m0 + arow) * HDIM + k0 + ak;
        float4 a0 = *(const float4*)Xp;
        float4 a1 = *(const float4*)(Xp + 4);
        float4 bv = *(const float4*)(W + (k0 + bk) * HDIM + n0 + bn);
        As[ak+0][arow] = a0.x; As[ak+1][arow] = a0.y; As[ak+2][arow] = a0.z; As[ak+3][arow] = a0.w;
        As[ak+4][arow] = a1.x; As[ak+5][arow] = a1.y; As[ak+6][arow] = a1.z; As[ak+7][arow] = a1.w;
        *(float4*)&Bs[bk][bn] = bv;
        __syncthreads();
        #pragma unroll
        for (int k = 0; k < 16; k++) {
            float4 rb = *(const float4*)&Bs[k][tx * 4];
            float ra[8];
            #pragma unroll
            for (int i = 0; i < 4; i++) {
                float2 t2 = *(const float2*)&As[k][ty * 8 + 2 * i];
                ra[2*i] = t2.x; ra[2*i+1] = t2.y;
            }
            #pragma unroll
            for (int i = 0; i < 8; i++) {
                acc[i][0] += ra[i] * rb.x;
                acc[i][1] += ra[i] * rb.y;
                acc[i][2] += ra[i] * rb.z;
                acc[i][3] += ra[i] * rb.w;
            }
        }
        __syncthreads();
    }
    float4 bb = *(const float4*)(bias + n0 + tx * 4);
    #pragma unroll
    for (int i = 0; i < 8; i++) {
        float4 o;
        o.x = acc[i][0] + bb.x; o.y = acc[i][1] + bb.y;
        o.z = acc[i][2] + bb.z; o.w = acc[i][3] + bb.w;
        *(float4*)&P[(m0 + ty * 8 + i) * HDIM + n0 + tx * 4] = o;
    }
}

// ---------------- Phase 2: sequential scan ----------------
// One 8-CTA cluster per batch element. Each CTA owns 64 output columns with its
// W_hh[:,64] slice in registers (f32x2-packed). Per step: FFMA2 MatVec partials,
// shfl+smem reduce, tanh, push h chunk to all 8 cluster CTAs via st.async with
// double-buffered smem h + 2 mbarriers (parity ping-pong, expect_tx = 2048 B).
__global__ __launch_bounds__(512, 1) __cluster_dims__(CLSZ, 1, 1)
void rnn_scan(const float* __restrict__ Whh, float* __restrict__ out)
{
    __shared__ __align__(16) float hbuf[2][HDIM];
    __shared__ __align__(16) float red[16][64];
    __shared__ __align__(16) unsigned long long mbar[2];

    const int tid   = threadIdx.x;
    const int rank  = blockIdx.x & (CLSZ - 1);
    const int batch = blockIdx.x / CLSZ;
    const int jg    = tid & 15;   // j-group: 4 consecutive columns
    const int kc    = tid >> 4;   // k-chunk: 16 consecutive k
    const int wi    = tid >> 5;
    const int lane  = tid & 31;

    // Preload W_hh slice (512 x 64) into registers, packed (k, k+1) pairs.
    unsigned long long w[4][8];
    {
        const int j0 = rank * 64 + jg * 4;
        const int kb = kc * 16;
        #pragma unroll
        for (int p = 0; p < 8; p++) {
            float4 l4 = *(const float4*)(Whh + (kb + 2*p)     * HDIM + j0);
            float4 h4 = *(const float4*)(Whh + (kb + 2*p + 1) * HDIM + j0);
            w[0][p] = pk2(l4.x, h4.x);
            w[1][p] = pk2(l4.y, h4.y);
            w[2][p] = pk2(l4.z, h4.z);
            w[3][p] = pk2(l4.w, h4.w);
        }
    }

    hbuf[0][tid] = 0.0f;   // h_{-1} = 0
    hbuf[1][tid] = 0.0f;
    const uint32_t h0a = smem_u32(&hbuf[0][0]);
    const uint32_t mb0 = smem_u32(&mbar[0]);
    if (tid == 0) {
        mbar_init(mb0, 1);
        mbar_init(mb0 + 8, 1);
        asm volatile("fence.mbarrier_init.release.cluster;" ::: "memory");
    }
    __syncthreads();
    cluster_sync_();   // peers' mbarriers + zeroed buffers visible before any st.async

    const long base = (long)batch * TLEN * HDIM + rank * 64;
    float preReg = 0.0f;
    if (tid < 64) preReg = out[base + tid];   // pre[b][0][j] (phase 1 wrote into out)

    const uint32_t myoff = (uint32_t)(rank * 64 + tid) * 4u;  // meaningful for tid<64

    for (int t = 0; t < TLEN; ++t) {
        const int pb = t & 1;
        const int nb = pb ^ 1;
        if (t > 0) {
            const uint32_t par = (uint32_t)(((t - 2 + pb) >> 1) & 1);
            mbar_wait_parity(mb0 + (uint32_t)pb * 8u, par);
        }

        // Partial MatVec: this thread covers columns jg*4..+3, k in [kc*16, kc*16+16)
        const unsigned long long* hp =
            reinterpret_cast<const unsigned long long*>(&hbuf[pb][kc * 16]);
        unsigned long long a0 = 0ull, a1 = 0ull, a2 = 0ull, a3 = 0ull;
        #pragma unroll
        for (int p = 0; p < 8; p++) {
            unsigned long long hv = hp[p];   // LDS.64, conflict-free broadcast
            fma2(a0, hv, w[0][p]);
            fma2(a1, hv, w[1][p]);
            fma2(a2, hv, w[2][p]);
            fma2(a3, hv, w[3][p]);
        }
        float s0 = lo32(a0) + hi32(a0);
        float s1 = lo32(a1) + hi32(a1);
        float s2 = lo32(a2) + hi32(a2);
        float s3 = lo32(a3) + hi32(a3);
        // fold kc-pairs within warp (lanes 0-15 <- lanes 16-31)
        s0 += __shfl_down_sync(0xffffffffu, s0, 16);
        s1 += __shfl_down_sync(0xffffffffu, s1, 16);
        s2 += __shfl_down_sync(0xffffffffu, s2, 16);
        s3 += __shfl_down_sync(0xffffffffu, s3, 16);
        if (lane < 16) {
            float4 v; v.x = s0; v.y = s1; v.z = s2; v.w = s3;
            *(float4*)&red[wi][jg * 4] = v;
        }
        __syncthreads();

        if (tid < 64) {
            float sum = red[0][tid];
            #pragma unroll
            for (int r = 1; r < 16; r++) sum += red[r][tid];
            const float hv = tanhf(sum + preReg);
            out[base + (long)t * HDIM + tid] = hv;
            if (t + 1 < TLEN) {
                preReg = out[base + (long)(t + 1) * HDIM + tid];  // prefetch next pre
                const uint32_t val   = __float_as_uint(hv);
                const uint32_t daddr = h0a + (uint32_t)nb * (HDIM * 4) + myoff;
                const uint32_t baddr = mb0 + (uint32_t)nb * 8u;
                #pragma unroll
                for (int r = 0; r < CLSZ; r++) {
                    st_async32(mapa32(daddr, (uint32_t)r), val, mapa32(baddr, (uint32_t)r));
                }
                if (tid == 0) mbar_expect_tx(baddr, CLSZ * 64 * 4);  // 2048 B/phase
            }
        }
        // No trailing barrier needed: passing the next step's mbar wait implies all
        // 8 CTAs' finisher threads completed their st.async, which happens-after
        // this CTA's finishers read `red` (WAR on red/hbuf closed transitively).
    }
    cluster_sync_();
}

// ---------------- launch ----------------
extern "C" void kernel_launch(void* const* d_in, const int* in_sizes, int n_in,
                              void* d_out, int out_size) {
    (void)in_sizes; (void)n_in; (void)out_size;
    const float* x    = (const float*)d_in[0];
    const float* Wxh  = (const float*)d_in[1];
    const float* Whh  = (const float*)d_in[2];
    const float* bias = (const float*)d_in[3];
    // d_in[4] = A (DFA feedback matrix): affects backward only, unused in forward.
    float* out = (float*)d_out;

    dim3 g1(NBATCH * TLEN / 128, HDIM / 64);
    pre_gemm<<<g1, 256>>>(x, Wxh, bias, out);          // writes pre (+bias) into out
    rnn_scan<<<NBATCH * CLSZ, 512>>>(Whh, out);        // overwrites out with h, in-place
}

// round 3
// speedup vs baseline: 1.0000x; 1.0000x over previous
#include <cuda_runtime.h>
#include <cstdint>

#define HDIM   512
#define TLEN   2048
#define NBATCH 16
#define CLSZ   8

// ---------------- PTX helpers ----------------
__device__ __forceinline__ uint32_t smem_u32(const void* p) {
    uint32_t a;
    asm("{ .reg .u64 t; cvta.to.shared.u64 t, %1; cvt.u32.u64 %0, t; }" : "=r"(a) : "l"(p));
    return a;
}
// packed 2x fp32 FMA (FFMA2): d = a*b + d, elementwise on (lo,hi)
__device__ __forceinline__ void fma2(unsigned long long& d, unsigned long long a, unsigned long long b) {
    asm("fma.rn.f32x2 %0, %1, %2, %0;" : "+l"(d) : "l"(a), "l"(b));
}
__device__ __forceinline__ unsigned long long pk2(float lo, float hi) {
    unsigned long long r;
    asm("mov.b64 %0, {%1, %2};" : "=l"(r) : "f"(lo), "f"(hi));
    return r;
}
__device__ __forceinline__ float lo32(unsigned long long v) { return __uint_as_float((unsigned)(v & 0xffffffffull)); }
__device__ __forceinline__ float hi32(unsigned long long v) { return __uint_as_float((unsigned)(v >> 32)); }
__device__ __forceinline__ uint32_t mapa32(uint32_t a, uint32_t r) {
    uint32_t d; asm("mapa.shared::cluster.u32 %0, %1, %2;" : "=r"(d) : "r"(a), "r"(r)); return d;
}
__device__ __forceinline__ void st_async32(uint32_t ra, uint32_t v, uint32_t rb) {
    asm volatile("st.async.shared::cluster.mbarrier::complete_tx::bytes.b32 [%0], %1, [%2];"
                 :: "r"(ra), "r"(v), "r"(rb) : "memory");
}
__device__ __forceinline__ void mbar_init(uint32_t m, uint32_t cnt) {
    asm volatile("mbarrier.init.shared.b64 [%0], %1;" :: "r"(m), "r"(cnt) : "memory");
}
__device__ __forceinline__ void mbar_expect_tx(uint32_t m, uint32_t bytes) {
    asm volatile("mbarrier.arrive.expect_tx.shared.b64 _, [%0], %1;" :: "r"(m), "r"(bytes) : "memory");
}
__device__ __forceinline__ void mbar_wait_parity(uint32_t m, uint32_t parity) {
    asm volatile(
        "{\n\t"
        ".reg .pred P;\n"
        "LW_%=:\n\t"
        "mbarrier.try_wait.parity.acquire.cluster.shared::cta.b64 P, [%0], %1, 0x989680;\n\t"
        "@!P bra LW_%=;\n\t"
        "}"
        :: "r"(m), "r"(parity) : "memory");
}
__device__ __forceinline__ void cluster_sync_() {
    asm volatile("barrier.cluster.arrive.aligned;" ::: "memory");
    asm volatile("barrier.cluster.wait.aligned;" ::: "memory");
}

// ---------------- Phase 1: pre = X @ W_xh + b  (M=32768, N=512, K=512) ----------------
// 128x64 block tile, BK=16, 256 threads, each thread 8x4 microtile. Plain fp32.
__global__ __launch_bounds__(256) void pre_gemm(
    const float* __restrict__ X, const float* __restrict__ W,
    const float* __restrict__ bias, float* __restrict__ P)
{
    __shared__ __align__(16) float As[16][130];  // [k][m], padded (bank-safe, 8B-aligned rows)
    __shared__ __align__(16) float Bs[16][64];   // [k][n]
    const int tid = threadIdx.x;
    const int tx  = tid & 15;   // n subtile (4 cols)
    const int ty  = tid >> 4;   // m subtile (8 rows)
    const int m0  = blockIdx.x * 128;
    const int n0  = blockIdx.y * 64;

    const int arow = tid >> 1;         // 0..127
    const int ak   = (tid & 1) * 8;    // k offset 0 or 8
    const int bk   = tid >> 4;         // 0..15
    const int bn   = (tid & 15) * 4;

    float acc[8][4];
    #pragma unroll
    for (int i = 0; i < 8; i++)
        #pragma unroll
        for (int j = 0; j < 4; j++) acc[i][j] = 0.0f;

    for (int kb = 0; kb < 32; kb++) {
        const int k0 = kb * 16;
        const float* Xp = X + (m0 + arow) * HDIM + k0 + ak;
        float4 a0 = *(const float4*)Xp;
        float4 a1 = *(const float4*)(Xp + 4);
        float4 bv = *(const float4*)(W + (k0 + bk) * HDIM + n0 + bn);
        As[ak+0][arow] = a0.x; As[ak+1][arow] = a0.y; As[ak+2][arow] = a0.z; As[ak+3][arow] = a0.w;
        As[ak+4][arow] = a1.x; As[ak+5][arow] = a1.y; As[ak+6][arow] = a1.z; As[ak+7][arow] = a1.w;
        *(float4*)&Bs[bk][bn] = bv;
        __syncthreads();
        #pragma unroll
        for (int k = 0; k < 16; k++) {
            float4 rb = *(const float4*)&Bs[k][tx * 4];
            float ra[8];
            #pragma unroll
            for (int i = 0; i < 4; i++) {
                float2 t2 = *(const float2*)&As[k][ty * 8 + 2 * i];
                ra[2*i] = t2.x; ra[2*i+1] = t2.y;
            }
            #pragma unroll
            for (int i = 0; i < 8; i++) {
                acc[i][0] += ra[i] * rb.x;
                acc[i][1] += ra[i] * rb.y;
                acc[i][2] += ra[i] * rb.z;
                acc[i][3] += ra[i] * rb.w;
            }
        }
        __syncthreads();
    }
    float4 bb = *(const float4*)(bias + n0 + tx * 4);
    #pragma unroll
    for (int i = 0; i < 8; i++) {
        float4 o;
        o.x = acc[i][0] + bb.x; o.y = acc[i][1] + bb.y;
        o.z = acc[i][2] + bb.z; o.w = acc[i][3] + bb.w;
        *(float4*)&P[(m0 + ty * 8 + i) * HDIM + n0 + tx * 4] = o;
    }
}

// ---------------- Phase 2: sequential scan ----------------
// One 8-CTA cluster per batch element. Each CTA owns 64 output columns with its
// W_hh[:,64] slice in registers (f32x2-packed). Per step: FFMA2 MatVec partials,
// shfl+smem reduce, tanh, push h chunk to all 8 cluster CTAs via st.async with
// double-buffered smem h + 2 mbarriers (parity ping-pong, expect_tx = 2048 B).
__global__ __launch_bounds__(512, 1) __cluster_dims__(CLSZ, 1, 1)
void rnn_scan(const float* __restrict__ Whh, float* __restrict__ out)
{
    __shared__ __align__(16) float hbuf[2][HDIM];
    __shared__ __align__(16) float red[16][64];
    __shared__ __align__(16) unsigned long long mbar[2];

    const int tid   = threadIdx.x;
    const int rank  = blockIdx.x & (CLSZ - 1);
    const int batch = blockIdx.x / CLSZ;
    const int jg    = tid & 15;   // j-group: 4 consecutive columns
    const int kc    = tid >> 4;   // k-chunk: 16 consecutive k
    const int wi    = tid >> 5;
    const int lane  = tid & 31;

    // Preload W_hh slice (512 x 64) into registers, packed (k, k+1) pairs.
    unsigned long long w[4][8];
    {
        const int j0 = rank * 64 + jg * 4;
        const int kb = kc * 16;
        #pragma unroll
        for (int p = 0; p < 8; p++) {
            float4 l4 = *(const float4*)(Whh + (kb + 2*p)     * HDIM + j0);
            float4 h4 = *(const float4*)(Whh + (kb + 2*p + 1) * HDIM + j0);
            w[0][p] = pk2(l4.x, h4.x);
            w[1][p] = pk2(l4.y, h4.y);
            w[2][p] = pk2(l4.z, h4.z);
            w[3][p] = pk2(l4.w, h4.w);
        }
    }

    hbuf[0][tid] = 0.0f;   // h_{-1} = 0
    hbuf[1][tid] = 0.0f;
    const uint32_t h0a = smem_u32(&hbuf[0][0]);
    const uint32_t mb0 = smem_u32(&mbar[0]);
    if (tid == 0) {
        mbar_init(mb0, 1);
        mbar_init(mb0 + 8, 1);
        asm volatile("fence.mbarrier_init.release.cluster;" ::: "memory");
    }
    __syncthreads();
    cluster_sync_();   // peers' mbarriers + zeroed buffers visible before any st.async

    const long base = (long)batch * TLEN * HDIM + rank * 64;
    float preReg = 0.0f;
    if (tid < 64) preReg = out[base + tid];   // pre[b][0][j] (phase 1 wrote into out)

    const uint32_t myoff = (uint32_t)(rank * 64 + tid) * 4u;  // meaningful for tid<64

    for (int t = 0; t < TLEN; ++t) {
        const int pb = t & 1;
        const int nb = pb ^ 1;
        if (t > 0) {
            const uint32_t par = (uint32_t)(((t - 2 + pb) >> 1) & 1);
            mbar_wait_parity(mb0 + (uint32_t)pb * 8u, par);
        }

        // Partial MatVec: this thread covers columns jg*4..+3, k in [kc*16, kc*16+16)
        const unsigned long long* hp =
            reinterpret_cast<const unsigned long long*>(&hbuf[pb][kc * 16]);
        unsigned long long a0 = 0ull, a1 = 0ull, a2 = 0ull, a3 = 0ull;
        #pragma unroll
        for (int p = 0; p < 8; p++) {
            unsigned long long hv = hp[p];   // LDS.64, conflict-free broadcast
            fma2(a0, hv, w[0][p]);
            fma2(a1, hv, w[1][p]);
            fma2(a2, hv, w[2][p]);
            fma2(a3, hv, w[3][p]);
        }
        float s0 = lo32(a0) + hi32(a0);
        float s1 = lo32(a1) + hi32(a1);
        float s2 = lo32(a2) + hi32(a2);
        float s3 = lo32(a3) + hi32(a3);
        // fold kc-pairs within warp (lanes 0-15 <- lanes 16-31)
        s0 += __shfl_down_sync(0xffffffffu, s0, 16);
        s1 += __shfl_down_sync(0xffffffffu, s1, 16);
        s2 += __shfl_down_sync(0xffffffffu, s2, 16);
        s3 += __shfl_down_sync(0xffffffffu, s3, 16);
        if (lane < 16) {
            float4 v; v.x = s0; v.y = s1; v.z = s2; v.w = s3;
            *(float4*)&red[wi][jg * 4] = v;
        }
        __syncthreads();

        if (tid < 64) {
            float sum = red[0][tid];
            #pragma unroll
            for (int r = 1; r < 16; r++) sum += red[r][tid];
            const float hv = tanhf(sum + preReg);
            out[base + (long)t * HDIM + tid] = hv;
            if (t + 1 < TLEN) {
                preReg = out[base + (long)(t + 1) * HDIM + tid];  // prefetch next pre
                const uint32_t val   = __float_as_uint(hv);
                const uint32_t daddr = h0a + (uint32_t)nb * (HDIM * 4) + myoff;
                const uint32_t baddr = mb0 + (uint32_t)nb * 8u;
                #pragma unroll
                for (int r = 0; r < CLSZ; r++) {
                    st_async32(mapa32(daddr, (uint32_t)r), val, mapa32(baddr, (uint32_t)r));
                }
                if (tid == 0) mbar_expect_tx(baddr, CLSZ * 64 * 4);  // 2048 B/phase
            }
        }
        // No trailing barrier needed: passing the next step's mbar wait implies all
        // 8 CTAs' finisher threads completed their st.async, which happens-after
        // this CTA's finishers read `red` (WAR on red/hbuf closed transitively).
    }
    cluster_sync_();
}

// ---------------- launch ----------------
extern "C" void kernel_launch(void* const* d_in, const int* in_sizes, int n_in,
                              void* d_out, int out_size) {
    (void)in_sizes; (void)n_in; (void)out_size;
    const float* x    = (const float*)d_in[0];
    const float* Wxh  = (const float*)d_in[1];
    const float* Whh  = (const float*)d_in[2];
    const float* bias = (const float*)d_in[3];
    // d_in[4] = A (DFA feedback matrix): affects backward only, unused in forward.
    float* out = (float*)d_out;

    dim3 g1(NBATCH * TLEN / 128, HDIM / 64);
    pre_gemm<<<g1, 256>>>(x, Wxh, bias, out);          // writes pre (+bias) into out
    rnn_scan<<<NBATCH * CLSZ, 512>>>(Whh, out);        // overwrites out with h, in-place
}